// round 5
// baseline (speedup 1.0000x reference)
#include <cuda_runtime.h>
#include <cuda_bf16.h>
#include <math.h>

#define N_NODES   50000
#define N_EDGES   800000
#define NUM_G     512
#define F         128

// ---------------- device scratch (globals: allocation-free) ----------------
__device__ float g_dinv[N_NODES];            // deg -> dinv, reused
__device__ float g_bufA[N_NODES * F];
__device__ float g_bufB[N_NODES * F];
__device__ float g_bufC[N_NODES * F];
__device__ float g_pool[NUM_G * F];
__device__ float g_cnt[NUM_G];

// ---------------- init: deg=1 (self loop), pool=0, cnt=0 ------------------
__global__ void k_init() {
    int i = blockIdx.x * blockDim.x + threadIdx.x;
    if (i < N_NODES) g_dinv[i] = 1.0f;
    if (i < NUM_G * F) g_pool[i] = 0.0f;
    if (i < NUM_G) g_cnt[i] = 0.0f;
}

// ---------------- degree count + graph-size count --------------------------
__global__ void k_deg(const int* __restrict__ ei,
                      const int* __restrict__ batch) {
    int i = blockIdx.x * blockDim.x + threadIdx.x;
    if (i < N_EDGES) {
        int d = ei[N_EDGES + i];
        atomicAdd(&g_dinv[d], 1.0f);
    }
    if (i < N_NODES) {
        atomicAdd(&g_cnt[batch[i]], 1.0f);
    }
}

__global__ void k_rsqrt() {
    int i = blockIdx.x * blockDim.x + threadIdx.x;
    if (i < N_NODES) g_dinv[i] = rsqrtf(g_dinv[i]);
}

// ---------------- GEMM: out = (X @ W) * dinv[row], written to hp + agg-init
// block: 256 threads, 64 rows x 128 cols. W streamed in 32-row K chunks.
// thread (q = tid&3, r = tid>>2) computes cols {q*4 + 16*j + 0..3 : j=0..7}
__global__ __launch_bounds__(256) void k_gemm(const float* __restrict__ Xext,
                                              const float* __restrict__ W,
                                              int layer) {
    __shared__ float Ws[32 * 128];
    __shared__ float Xs[64 * 33];

    const float* __restrict__ X  = (layer == 1) ? Xext : g_bufA;
    float* __restrict__ outHp    = (layer == 1) ? g_bufA : g_bufB;
    float* __restrict__ outAgg   = (layer == 1) ? g_bufB : g_bufC;

    int row0 = blockIdx.x * 64;
    int tid  = threadIdx.x;
    int q = tid & 3;
    int r = tid >> 2;

    float acc[32];
#pragma unroll
    for (int j = 0; j < 32; j++) acc[j] = 0.0f;

    for (int k0 = 0; k0 < F; k0 += 32) {
        // stage W chunk: rows k0..k0+31 (contiguous 4096 floats)
        const float4* W4 = (const float4*)(W + k0 * F);
        float4* Ws4 = (float4*)Ws;
#pragma unroll
        for (int t = tid; t < 1024; t += 256) Ws4[t] = __ldg(&W4[t]);
        // stage X chunk: 64 rows x 32 k
#pragma unroll
        for (int t = tid; t < 512; t += 256) {
            int rr  = t >> 3;
            int kk4 = t & 7;
            int grow = row0 + rr;
            float4 xv = make_float4(0.f, 0.f, 0.f, 0.f);
            if (grow < N_NODES)
                xv = __ldg((const float4*)&X[grow * F + k0 + kk4 * 4]);
            Xs[rr * 33 + kk4 * 4 + 0] = xv.x;
            Xs[rr * 33 + kk4 * 4 + 1] = xv.y;
            Xs[rr * 33 + kk4 * 4 + 2] = xv.z;
            Xs[rr * 33 + kk4 * 4 + 3] = xv.w;
        }
        __syncthreads();

#pragma unroll
        for (int kk = 0; kk < 32; kk++) {
            float xv = Xs[r * 33 + kk];
#pragma unroll
            for (int j = 0; j < 8; j++) {
                const float4 w = *(const float4*)&Ws[kk * F + q * 4 + j * 16];
                acc[j * 4 + 0] += xv * w.x;
                acc[j * 4 + 1] += xv * w.y;
                acc[j * 4 + 2] += xv * w.z;
                acc[j * 4 + 3] += xv * w.w;
            }
        }
        __syncthreads();
    }

    int grow = row0 + r;
    if (grow < N_NODES) {
        float dv = g_dinv[grow];
#pragma unroll
        for (int j = 0; j < 8; j++) {
            float4 o;
            o.x = acc[j * 4 + 0] * dv;
            o.y = acc[j * 4 + 1] * dv;
            o.z = acc[j * 4 + 2] * dv;
            o.w = acc[j * 4 + 3] * dv;
            int col = q * 4 + j * 16;
            *(float4*)&outHp[grow * F + col]  = o;
            *(float4*)&outAgg[grow * F + col] = o;   // self-loop init
        }
    }
}

// ---------------- edge scatter: agg[dst] += hp[src], one warp per edge ----
__global__ __launch_bounds__(256) void k_scatter(const int* __restrict__ ei,
                                                 int layer) {
    const float4* __restrict__ src = (const float4*)((layer == 1) ? g_bufA : g_bufB);
    float4* __restrict__ dst       = (float4*)((layer == 1) ? g_bufB : g_bufC);

    int gwarp = (blockIdx.x * blockDim.x + threadIdx.x) >> 5;
    int lane  = threadIdx.x & 31;
    int nwarp = (gridDim.x * blockDim.x) >> 5;

    for (int e = gwarp; e < N_EDGES; e += nwarp) {
        int s = __ldg(&ei[e]);
        int d = __ldg(&ei[N_EDGES + e]);
        float4 v = __ldg(&src[s * 32 + lane]);
        const float4* p = &dst[d * 32 + lane];
        asm volatile("red.global.add.v4.f32 [%0], {%1, %2, %3, %4};"
                     :: "l"(p), "f"(v.x), "f"(v.y), "f"(v.z), "f"(v.w)
                     : "memory");
    }
}

// ---------------- epilogue layer1: h1 = relu(agg*dinv + b1) -> bufA -------
__global__ void k_epi1(const float* __restrict__ b1) {
    int i = blockIdx.x * blockDim.x + threadIdx.x;
    if (i < N_NODES * F) {
        int f = i & (F - 1);
        int n = i >> 7;
        float v = g_bufB[i] * g_dinv[n] + b1[f];
        g_bufA[i] = fmaxf(v, 0.0f);
    }
}

// ---------------- epilogue layer2 fused with pooling -----------------------
// 128 threads = feature dim, block handles 64 consecutive (sorted) nodes.
__global__ __launch_bounds__(128) void k_epi2pool(const float* __restrict__ b2,
                                                  const int* __restrict__ batch) {
    int f  = threadIdx.x;
    int n0 = blockIdx.x * 64;
    if (n0 >= N_NODES) return;

    float bf = b2[f];
    float acc = 0.0f;
    int curg = batch[n0];

    int nend = n0 + 64;
    if (nend > N_NODES) nend = N_NODES;
    for (int n = n0; n < nend; n++) {
        int g = batch[n];
        if (g != curg) {
            atomicAdd(&g_pool[curg * F + f], acc);
            acc = 0.0f;
            curg = g;
        }
        float v = g_bufC[n * F + f] * g_dinv[n] + bf;
        acc += fmaxf(v, 0.0f);
    }
    atomicAdd(&g_pool[curg * F + f], acc);
}

// ---------------- head: out[g] = sigmoid(dot(pool[g]/cnt, Wl) + bl) -------
__global__ void k_final(const float* __restrict__ Wl,
                        const float* __restrict__ bl,
                        float* __restrict__ out) {
    __shared__ float Wls[F];
    int tid = threadIdx.x;
    if (tid < F) Wls[tid] = Wl[tid];
    __syncthreads();

    int g = blockIdx.x * blockDim.x + tid;
    if (g < NUM_G) {
        float sum = 0.0f;
#pragma unroll 8
        for (int k = 0; k < F; k++) sum += g_pool[g * F + k] * Wls[k];
        float c = fmaxf(g_cnt[g], 1.0f);
        float z = sum / c + bl[0];
        out[g] = 1.0f / (1.0f + expf(-z));
    }
}

// ---------------- launch -----------------------------------------------
extern "C" void kernel_launch(void* const* d_in, const int* in_sizes, int n_in,
                              void* d_out, int out_size) {
    const float* x     = (const float*)d_in[0];
    const int*   ei    = (const int*)d_in[1];     // int32: JAX x64 disabled
    const int*   batch = (const int*)d_in[2];     // int32
    const float* W1    = (const float*)d_in[3];
    const float* b1    = (const float*)d_in[4];
    const float* W2    = (const float*)d_in[5];
    const float* b2    = (const float*)d_in[6];
    const float* Wl    = (const float*)d_in[7];
    const float* bl    = (const float*)d_in[8];
    float* out = (float*)d_out;

    k_init<<<(NUM_G * F + 255) / 256, 256>>>();
    k_deg<<<(N_EDGES + 255) / 256, 256>>>(ei, batch);
    k_rsqrt<<<(N_NODES + 255) / 256, 256>>>();

    int gemm_blocks = (N_NODES + 63) / 64;

    // layer 1
    k_gemm<<<gemm_blocks, 256>>>(x, W1, 1);
    k_scatter<<<2368, 256>>>(ei, 1);
    k_epi1<<<(N_NODES * F + 255) / 256, 256>>>(b1);

    // layer 2
    k_gemm<<<gemm_blocks, 256>>>(nullptr, W2, 2);
    k_scatter<<<2368, 256>>>(ei, 2);
    k_epi2pool<<<(N_NODES + 63) / 64, 128>>>(b2, batch);

    k_final<<<(NUM_G + 255) / 256, 256>>>(Wl, bl, out);
}

// round 6
// speedup vs baseline: 2.2487x; 2.2487x over previous
#include <cuda_runtime.h>
#include <cuda_bf16.h>
#include <math.h>

#define N_NODES   50000
#define N_EDGES   800000
#define NUM_G     512
#define F         128

// ---------------- device scratch (globals: allocation-free) ----------------
__device__ float g_dinv[N_NODES];
__device__ int   g_deg[N_NODES];     // in-degree (real edges only)
__device__ int   g_start[N_NODES];   // CSR row offsets (arbitrary order)
__device__ int   g_cur[N_NODES];     // fill cursors
__device__ int   g_csr[N_EDGES];     // src index per slot
__device__ int   g_total;
__device__ float g_bufA[N_NODES * F];
__device__ float g_bufB[N_NODES * F];
__device__ float g_pool[NUM_G * F];
__device__ float g_cnt[NUM_G];

// ---------------- init ------------------------------------------------------
__global__ void k_init() {
    int i = blockIdx.x * blockDim.x + threadIdx.x;
    if (i < N_NODES) g_deg[i] = 0;
    if (i < NUM_G * F) g_pool[i] = 0.0f;
    if (i < NUM_G) g_cnt[i] = 0.0f;
    if (i == 0) g_total = 0;
}

// ---------------- degree + graph-size histograms ----------------------------
__global__ void k_deg(const int* __restrict__ ei,
                      const int* __restrict__ batch) {
    int i = blockIdx.x * blockDim.x + threadIdx.x;
    if (i < N_EDGES) atomicAdd(&g_deg[ei[N_EDGES + i]], 1);
    if (i < N_NODES) atomicAdd(&g_cnt[batch[i]], 1.0f);
}

// ---------------- dinv = rsqrt(deg+1)  (+1 = self loop) --------------------
__global__ void k_rsqrt() {
    int i = blockIdx.x * blockDim.x + threadIdx.x;
    if (i < N_NODES) g_dinv[i] = rsqrtf((float)g_deg[i] + 1.0f);
}

// ---------------- CSR offset allocation (warp-aggregated atomic) ------------
__global__ void k_alloc() {
    int i = blockIdx.x * blockDim.x + threadIdx.x;
    int lane = threadIdx.x & 31;
    int d = (i < N_NODES) ? g_deg[i] : 0;
    int x = d;
#pragma unroll
    for (int o = 1; o < 32; o <<= 1) {
        int y = __shfl_up_sync(0xffffffff, x, o);
        if (lane >= o) x += y;
    }
    int warpsum = __shfl_sync(0xffffffff, x, 31);
    int base = 0;
    if (lane == 31) base = atomicAdd(&g_total, warpsum);
    base = __shfl_sync(0xffffffff, base, 31);
    int start = base + x - d;
    if (i < N_NODES) { g_start[i] = start; g_cur[i] = start; }
}

// ---------------- CSR fill ---------------------------------------------------
__global__ void k_fill(const int* __restrict__ ei) {
    int e = blockIdx.x * blockDim.x + threadIdx.x;
    if (e < N_EDGES) {
        int s = ei[e];
        int d = ei[N_EDGES + e];
        int slot = atomicAdd(&g_cur[d], 1);
        g_csr[slot] = s;
    }
}

// ---------------- GEMM: out = (X @ W) * dinv[row] ---------------------------
// 128x128 block tile, 256 threads (16x16), 8x8 micro-tile per thread.
__global__ __launch_bounds__(256) void k_gemm(const float* __restrict__ X,
                                              const float* __restrict__ W,
                                              float* __restrict__ out) {
    __shared__ float Ws[16 * 128];         // Ws[kk][col]
    __shared__ float Xs[16 * 132];         // Xs[kk][row], stride 132 (528B, 16B-aligned)

    int tid = threadIdx.x;
    int tx = tid & 15;          // col group
    int ty = tid >> 4;          // row group
    int row0 = blockIdx.x * 128;

    float acc[8][8];
#pragma unroll
    for (int i = 0; i < 8; i++)
#pragma unroll
        for (int j = 0; j < 8; j++) acc[i][j] = 0.0f;

    for (int k0 = 0; k0 < F; k0 += 16) {
        // stage W chunk: rows k0..k0+15, contiguous 2048 floats
        const float4* W4 = (const float4*)(W + k0 * F);
        float4* Ws4 = (float4*)Ws;
#pragma unroll
        for (int t = tid; t < 512; t += 256) Ws4[t] = __ldg(&W4[t]);
        // stage X chunk transposed: Xs[kk][row]
#pragma unroll
        for (int t = tid; t < 512; t += 256) {
            int rr = t >> 2;            // 0..127
            int c  = t & 3;             // which float4 along k
            int grow = row0 + rr;
            float4 xv = make_float4(0.f, 0.f, 0.f, 0.f);
            if (grow < N_NODES)
                xv = __ldg((const float4*)&X[grow * F + k0 + c * 4]);
            Xs[(c * 4 + 0) * 132 + rr] = xv.x;
            Xs[(c * 4 + 1) * 132 + rr] = xv.y;
            Xs[(c * 4 + 2) * 132 + rr] = xv.z;
            Xs[(c * 4 + 3) * 132 + rr] = xv.w;
        }
        __syncthreads();

#pragma unroll
        for (int kk = 0; kk < 16; kk++) {
            float4 a0 = *(const float4*)&Xs[kk * 132 + ty * 4];
            float4 a1 = *(const float4*)&Xs[kk * 132 + 64 + ty * 4];
            float4 b0 = *(const float4*)&Ws[kk * 128 + tx * 4];
            float4 b1 = *(const float4*)&Ws[kk * 128 + 64 + tx * 4];
            float a[8] = {a0.x, a0.y, a0.z, a0.w, a1.x, a1.y, a1.z, a1.w};
            float b[8] = {b0.x, b0.y, b0.z, b0.w, b1.x, b1.y, b1.z, b1.w};
#pragma unroll
            for (int i = 0; i < 8; i++)
#pragma unroll
                for (int j = 0; j < 8; j++) acc[i][j] += a[i] * b[j];
        }
        __syncthreads();
    }

    // epilogue: scale by dinv[row], vectorized writes
#pragma unroll
    for (int i = 0; i < 8; i++) {
        int grow = row0 + ((i < 4) ? (ty * 4 + i) : (64 + ty * 4 + (i - 4)));
        if (grow < N_NODES) {
            float dv = g_dinv[grow];
            float4 o0 = make_float4(acc[i][0] * dv, acc[i][1] * dv,
                                    acc[i][2] * dv, acc[i][3] * dv);
            float4 o1 = make_float4(acc[i][4] * dv, acc[i][5] * dv,
                                    acc[i][6] * dv, acc[i][7] * dv);
            *(float4*)&out[grow * F + tx * 4]      = o0;
            *(float4*)&out[grow * F + 64 + tx * 4] = o1;
        }
    }
}

// ---------------- gather: h[n] = relu(dinv[n]*(hp[n] + sum_in hp[src]) + b)
// warp per node; layer==1 writes rows, layer==2 reduces into pool.
__global__ __launch_bounds__(256) void k_gather(const float* __restrict__ hp_,
                                                float* __restrict__ out_,
                                                const float* __restrict__ bias,
                                                const int* __restrict__ batch,
                                                int layer) {
    int warp = (blockIdx.x * blockDim.x + threadIdx.x) >> 5;
    int lane = threadIdx.x & 31;
    if (warp >= N_NODES) return;
    int node = warp;

    const float4* __restrict__ hp = (const float4*)hp_;

    float4 acc = __ldg(&hp[node * 32 + lane]);   // self loop (hp already *dinv[src])
    int start = g_start[node];
    int deg   = g_deg[node];

    for (int base = 0; base < deg; base += 32) {
        int rem = deg - base;
        int n = (rem < 32) ? rem : 32;
        int idx = (lane < n) ? __ldg(&g_csr[start + base + lane]) : 0;
#pragma unroll 4
        for (int j = 0; j < n; j++) {
            int s = __shfl_sync(0xffffffff, idx, j);
            float4 v = __ldg(&hp[s * 32 + lane]);
            acc.x += v.x; acc.y += v.y; acc.z += v.z; acc.w += v.w;
        }
    }

    float dv = g_dinv[node];
    float4 b4 = __ldg(&((const float4*)bias)[lane]);
    float4 r;
    r.x = fmaxf(acc.x * dv + b4.x, 0.0f);
    r.y = fmaxf(acc.y * dv + b4.y, 0.0f);
    r.z = fmaxf(acc.z * dv + b4.z, 0.0f);
    r.w = fmaxf(acc.w * dv + b4.w, 0.0f);

    if (layer == 1) {
        ((float4*)out_)[node * 32 + lane] = r;
    } else {
        int g = __ldg(&batch[node]);
        const float4* p = &((const float4*)g_pool)[g * 32 + lane];
        asm volatile("red.global.add.v4.f32 [%0], {%1, %2, %3, %4};"
                     :: "l"(p), "f"(r.x), "f"(r.y), "f"(r.z), "f"(r.w)
                     : "memory");
    }
}

// ---------------- head: out[g] = sigmoid(dot(pool[g]/cnt, Wl) + bl) --------
__global__ void k_final(const float* __restrict__ Wl,
                        const float* __restrict__ bl,
                        float* __restrict__ out) {
    __shared__ float Wls[F];
    int tid = threadIdx.x;
    if (tid < F) Wls[tid] = Wl[tid];
    __syncthreads();

    int g = blockIdx.x * blockDim.x + tid;
    if (g < NUM_G) {
        float sum = 0.0f;
#pragma unroll 8
        for (int k = 0; k < F; k++) sum += g_pool[g * F + k] * Wls[k];
        float c = fmaxf(g_cnt[g], 1.0f);
        float z = sum / c + bl[0];
        out[g] = 1.0f / (1.0f + expf(-z));
    }
}

// ---------------- launch ----------------------------------------------------
extern "C" void kernel_launch(void* const* d_in, const int* in_sizes, int n_in,
                              void* d_out, int out_size) {
    const float* x     = (const float*)d_in[0];
    const int*   ei    = (const int*)d_in[1];
    const int*   batch = (const int*)d_in[2];
    const float* W1    = (const float*)d_in[3];
    const float* b1    = (const float*)d_in[4];
    const float* W2    = (const float*)d_in[5];
    const float* b2    = (const float*)d_in[6];
    const float* Wl    = (const float*)d_in[7];
    const float* bl    = (const float*)d_in[8];
    float* out = (float*)d_out;

    float* bufA; cudaGetSymbolAddress((void**)&bufA, g_bufA);
    float* bufB; cudaGetSymbolAddress((void**)&bufB, g_bufB);

    k_init<<<(NUM_G * F + 255) / 256, 256>>>();
    k_deg<<<(N_EDGES + 255) / 256, 256>>>(ei, batch);
    k_rsqrt<<<(N_NODES + 255) / 256, 256>>>();
    k_alloc<<<(N_NODES + 255) / 256, 256>>>();
    k_fill<<<(N_EDGES + 255) / 256, 256>>>(ei);

    int gemm_blocks = (N_NODES + 127) / 128;
    int gth_blocks  = (N_NODES * 32 + 255) / 256;

    // layer 1: x -> hp1 (bufA) -> h1 (bufB)
    k_gemm<<<gemm_blocks, 256>>>(x, W1, bufA);
    k_gather<<<gth_blocks, 256>>>(bufA, bufB, b1, batch, 1);

    // layer 2: h1 (bufB) -> hp2 (bufA) -> pool
    k_gemm<<<gemm_blocks, 256>>>(bufB, W2, bufA);
    k_gather<<<gth_blocks, 256>>>(bufA, nullptr, b2, batch, 2);

    k_final<<<(NUM_G + 255) / 256, 256>>>(Wl, bl, out);
}

// round 7
// speedup vs baseline: 2.3728x; 1.0552x over previous
#include <cuda_runtime.h>
#include <cuda_bf16.h>
#include <math.h>

#define N_NODES   50000
#define N_EDGES   800000
#define NUM_G     512
#define F         128

// ---------------- device scratch (globals: allocation-free) ----------------
__device__ float g_dinv[N_NODES];
__device__ int   g_deg[N_NODES];     // in-degree (real edges only)
__device__ int   g_start[N_NODES];   // CSR row offsets (arbitrary order)
__device__ int   g_cur[N_NODES];     // fill cursors
__device__ int   g_csr[N_EDGES];     // src index per slot
__device__ int   g_total;
__device__ float g_bufA[N_NODES * F];
__device__ float g_bufB[N_NODES * F];
__device__ float g_pool[NUM_G * F];
__device__ float g_cnt[NUM_G];

// ---------------- init ------------------------------------------------------
__global__ void k_init() {
    int i = blockIdx.x * blockDim.x + threadIdx.x;
    if (i < N_NODES) g_deg[i] = 0;
    if (i < NUM_G * F) g_pool[i] = 0.0f;
    if (i < NUM_G) g_cnt[i] = 0.0f;
    if (i == 0) g_total = 0;
}

// ---------------- degree + graph-size histograms ----------------------------
__global__ void k_deg(const int* __restrict__ ei,
                      const int* __restrict__ batch) {
    int i = blockIdx.x * blockDim.x + threadIdx.x;
    if (i < N_EDGES) atomicAdd(&g_deg[ei[N_EDGES + i]], 1);
    if (i < N_NODES) atomicAdd(&g_cnt[batch[i]], 1.0f);
}

// ---------------- CSR offset alloc (warp-scan) + dinv = rsqrt(deg+1) --------
__global__ void k_alloc() {
    int i = blockIdx.x * blockDim.x + threadIdx.x;
    int lane = threadIdx.x & 31;
    int d = (i < N_NODES) ? g_deg[i] : 0;
    if (i < N_NODES) g_dinv[i] = rsqrtf((float)d + 1.0f);
    int x = d;
#pragma unroll
    for (int o = 1; o < 32; o <<= 1) {
        int y = __shfl_up_sync(0xffffffff, x, o);
        if (lane >= o) x += y;
    }
    int warpsum = __shfl_sync(0xffffffff, x, 31);
    int base = 0;
    if (lane == 31) base = atomicAdd(&g_total, warpsum);
    base = __shfl_sync(0xffffffff, base, 31);
    int start = base + x - d;
    if (i < N_NODES) { g_start[i] = start; g_cur[i] = start; }
}

// ---------------- CSR fill ---------------------------------------------------
__global__ void k_fill(const int* __restrict__ ei) {
    int e = blockIdx.x * blockDim.x + threadIdx.x;
    if (e < N_EDGES) {
        int s = ei[e];
        int d = ei[N_EDGES + e];
        int slot = atomicAdd(&g_cur[d], 1);
        g_csr[slot] = s;
    }
}

// ---------------- GEMM: out = (X @ W) * dinv[row] ---------------------------
// 128x128 block tile, 256 threads (16x16), 8x8 micro-tile per thread.
// Inner product uses packed fma.rn.f32x2 (FFMA2): 32 packed FMAs per k-step
// instead of 64 scalar FFMA -> halves fma-pipe issue count. Exact fp32.
__global__ __launch_bounds__(256) void k_gemm(const float* __restrict__ X,
                                              const float* __restrict__ W,
                                              float* __restrict__ out) {
    __shared__ float Ws[16 * 128];         // Ws[kk][col]
    __shared__ float Xs[16 * 132];         // Xs[kk][row]

    int tid = threadIdx.x;
    int tx = tid & 15;          // col group
    int ty = tid >> 4;          // row group
    int row0 = blockIdx.x * 128;

    // acc2[i][j] = packed pair (col 2j, col 2j+1) for output row i
    unsigned long long acc2[8][4];
#pragma unroll
    for (int i = 0; i < 8; i++)
#pragma unroll
        for (int j = 0; j < 4; j++) acc2[i][j] = 0ull;

    for (int k0 = 0; k0 < F; k0 += 16) {
        const float4* W4 = (const float4*)(W + k0 * F);
        float4* Ws4 = (float4*)Ws;
#pragma unroll
        for (int t = tid; t < 512; t += 256) Ws4[t] = __ldg(&W4[t]);
#pragma unroll
        for (int t = tid; t < 512; t += 256) {
            int rr = t >> 2;
            int c  = t & 3;
            int grow = row0 + rr;
            float4 xv = make_float4(0.f, 0.f, 0.f, 0.f);
            if (grow < N_NODES)
                xv = __ldg((const float4*)&X[grow * F + k0 + c * 4]);
            Xs[(c * 4 + 0) * 132 + rr] = xv.x;
            Xs[(c * 4 + 1) * 132 + rr] = xv.y;
            Xs[(c * 4 + 2) * 132 + rr] = xv.z;
            Xs[(c * 4 + 3) * 132 + rr] = xv.w;
        }
        __syncthreads();

#pragma unroll
        for (int kk = 0; kk < 16; kk++) {
            float4 a0 = *(const float4*)&Xs[kk * 132 + ty * 4];
            float4 a1 = *(const float4*)&Xs[kk * 132 + 64 + ty * 4];
            float4 b0 = *(const float4*)&Ws[kk * 128 + tx * 4];
            float4 b1 = *(const float4*)&Ws[kk * 128 + 64 + tx * 4];

            unsigned long long bp[4];
            asm("mov.b64 %0, {%1,%2};" : "=l"(bp[0]) : "f"(b0.x), "f"(b0.y));
            asm("mov.b64 %0, {%1,%2};" : "=l"(bp[1]) : "f"(b0.z), "f"(b0.w));
            asm("mov.b64 %0, {%1,%2};" : "=l"(bp[2]) : "f"(b1.x), "f"(b1.y));
            asm("mov.b64 %0, {%1,%2};" : "=l"(bp[3]) : "f"(b1.z), "f"(b1.w));

            float a[8] = {a0.x, a0.y, a0.z, a0.w, a1.x, a1.y, a1.z, a1.w};
#pragma unroll
            for (int i = 0; i < 8; i++) {
                unsigned long long ad;
                asm("mov.b64 %0, {%1,%1};" : "=l"(ad) : "f"(a[i]));
#pragma unroll
                for (int j = 0; j < 4; j++)
                    asm("fma.rn.f32x2 %0, %1, %2, %0;"
                        : "+l"(acc2[i][j]) : "l"(ad), "l"(bp[j]));
            }
        }
        __syncthreads();
    }

    // epilogue: unpack, scale by dinv[row], vectorized writes
#pragma unroll
    for (int i = 0; i < 8; i++) {
        int grow = row0 + ((i < 4) ? (ty * 4 + i) : (64 + ty * 4 + (i - 4)));
        if (grow < N_NODES) {
            float dv = g_dinv[grow];
            float c0, c1, c2, c3, c4, c5, c6, c7;
            asm("mov.b64 {%0,%1}, %2;" : "=f"(c0), "=f"(c1) : "l"(acc2[i][0]));
            asm("mov.b64 {%0,%1}, %2;" : "=f"(c2), "=f"(c3) : "l"(acc2[i][1]));
            asm("mov.b64 {%0,%1}, %2;" : "=f"(c4), "=f"(c5) : "l"(acc2[i][2]));
            asm("mov.b64 {%0,%1}, %2;" : "=f"(c6), "=f"(c7) : "l"(acc2[i][3]));
            float4 o0 = make_float4(c0 * dv, c1 * dv, c2 * dv, c3 * dv);
            float4 o1 = make_float4(c4 * dv, c5 * dv, c6 * dv, c7 * dv);
            *(float4*)&out[grow * F + tx * 4]      = o0;
            *(float4*)&out[grow * F + 64 + tx * 4] = o1;
        }
    }
}

// ---------------- gather: h[n] = relu(dinv[n]*(hp[n] + sum_in hp[src]) + b)
// warp per node; layer==1 writes rows, layer==2 reduces into pool.
__global__ __launch_bounds__(256) void k_gather(const float* __restrict__ hp_,
                                                float* __restrict__ out_,
                                                const float* __restrict__ bias,
                                                const int* __restrict__ batch,
                                                int layer) {
    int warp = (blockIdx.x * blockDim.x + threadIdx.x) >> 5;
    int lane = threadIdx.x & 31;
    if (warp >= N_NODES) return;
    int node = warp;

    const float4* __restrict__ hp = (const float4*)hp_;

    float4 acc = __ldg(&hp[node * 32 + lane]);   // self loop (hp already *dinv[src])
    int start = g_start[node];
    int deg   = g_deg[node];

    for (int base = 0; base < deg; base += 32) {
        int rem = deg - base;
        int n = (rem < 32) ? rem : 32;
        int idx = (lane < n) ? __ldg(&g_csr[start + base + lane]) : 0;
#pragma unroll 4
        for (int j = 0; j < n; j++) {
            int s = __shfl_sync(0xffffffff, idx, j);
            float4 v = __ldg(&hp[s * 32 + lane]);
            acc.x += v.x; acc.y += v.y; acc.z += v.z; acc.w += v.w;
        }
    }

    float dv = g_dinv[node];
    float4 b4 = __ldg(&((const float4*)bias)[lane]);
    float4 r;
    r.x = fmaxf(acc.x * dv + b4.x, 0.0f);
    r.y = fmaxf(acc.y * dv + b4.y, 0.0f);
    r.z = fmaxf(acc.z * dv + b4.z, 0.0f);
    r.w = fmaxf(acc.w * dv + b4.w, 0.0f);

    if (layer == 1) {
        ((float4*)out_)[node * 32 + lane] = r;
    } else {
        int g = __ldg(&batch[node]);
        const float4* p = &((const float4*)g_pool)[g * 32 + lane];
        asm volatile("red.global.add.v4.f32 [%0], {%1, %2, %3, %4};"
                     :: "l"(p), "f"(r.x), "f"(r.y), "f"(r.z), "f"(r.w)
                     : "memory");
    }
}

// ---------------- head: out[g] = sigmoid(dot(pool[g]/cnt, Wl) + bl) --------
__global__ void k_final(const float* __restrict__ Wl,
                        const float* __restrict__ bl,
                        float* __restrict__ out) {
    __shared__ float Wls[F];
    int tid = threadIdx.x;
    if (tid < F) Wls[tid] = Wl[tid];
    __syncthreads();

    int g = blockIdx.x * blockDim.x + tid;
    if (g < NUM_G) {
        float sum = 0.0f;
#pragma unroll 8
        for (int k = 0; k < F; k++) sum += g_pool[g * F + k] * Wls[k];
        float c = fmaxf(g_cnt[g], 1.0f);
        float z = sum / c + bl[0];
        out[g] = 1.0f / (1.0f + expf(-z));
    }
}

// ---------------- launch ----------------------------------------------------
extern "C" void kernel_launch(void* const* d_in, const int* in_sizes, int n_in,
                              void* d_out, int out_size) {
    const float* x     = (const float*)d_in[0];
    const int*   ei    = (const int*)d_in[1];
    const int*   batch = (const int*)d_in[2];
    const float* W1    = (const float*)d_in[3];
    const float* b1    = (const float*)d_in[4];
    const float* W2    = (const float*)d_in[5];
    const float* b2    = (const float*)d_in[6];
    const float* Wl    = (const float*)d_in[7];
    const float* bl    = (const float*)d_in[8];
    float* out = (float*)d_out;

    float* bufA; cudaGetSymbolAddress((void**)&bufA, g_bufA);
    float* bufB; cudaGetSymbolAddress((void**)&bufB, g_bufB);

    k_init<<<(NUM_G * F + 255) / 256, 256>>>();
    k_deg<<<(N_EDGES + 255) / 256, 256>>>(ei, batch);
    k_alloc<<<(N_NODES + 255) / 256, 256>>>();
    k_fill<<<(N_EDGES + 255) / 256, 256>>>(ei);

    int gemm_blocks = (N_NODES + 127) / 128;
    int gth_blocks  = (N_NODES * 32 + 255) / 256;

    // layer 1: x -> hp1 (bufA) -> h1 (bufB)
    k_gemm<<<gemm_blocks, 256>>>(x, W1, bufA);
    k_gather<<<gth_blocks, 256>>>(bufA, bufB, b1, batch, 1);

    // layer 2: h1 (bufB) -> hp2 (bufA) -> pool
    k_gemm<<<gemm_blocks, 256>>>(bufB, W2, bufA);
    k_gather<<<gth_blocks, 256>>>(bufA, nullptr, b2, batch, 2);

    k_final<<<(NUM_G + 255) / 256, 256>>>(Wl, bl, out);
}

// round 8
// speedup vs baseline: 2.6032x; 1.0971x over previous
#include <cuda_runtime.h>
#include <cuda_fp16.h>
#include <math.h>

#define N_NODES   50000
#define N_EDGES   800000
#define NUM_G     512
#define F         128

// ---------------- device scratch (globals: allocation-free) ----------------
__device__ float  g_dinv[N_NODES];
__device__ int    g_deg[N_NODES];
__device__ int    g_start[N_NODES];
__device__ int    g_cur[N_NODES];
__device__ int    g_csr[N_EDGES];
__device__ int    g_total;
__device__ __half g_h16A[N_NODES * F];   // hp (scaled X@W), fp16 storage
__device__ __half g_h16B[N_NODES * F];   // h1 (post-relu), fp16 storage
__device__ float  g_pool[NUM_G * F];
__device__ float  g_cnt[NUM_G];

// ---------------- init ------------------------------------------------------
__global__ void k_init() {
    int i = blockIdx.x * blockDim.x + threadIdx.x;
    if (i < N_NODES) g_deg[i] = 0;
    if (i < NUM_G * F) g_pool[i] = 0.0f;
    if (i < NUM_G) g_cnt[i] = 0.0f;
    if (i == 0) g_total = 0;
}

// ---------------- degree + graph-size histograms ----------------------------
__global__ void k_deg(const int* __restrict__ ei,
                      const int* __restrict__ batch) {
    int i = blockIdx.x * blockDim.x + threadIdx.x;
    if (i < N_EDGES) atomicAdd(&g_deg[ei[N_EDGES + i]], 1);
    if (i < N_NODES) atomicAdd(&g_cnt[batch[i]], 1.0f);
}

// ---------------- CSR offset alloc (warp-scan) + dinv = rsqrt(deg+1) --------
__global__ void k_alloc() {
    int i = blockIdx.x * blockDim.x + threadIdx.x;
    int lane = threadIdx.x & 31;
    int d = (i < N_NODES) ? g_deg[i] : 0;
    if (i < N_NODES) g_dinv[i] = rsqrtf((float)d + 1.0f);
    int x = d;
#pragma unroll
    for (int o = 1; o < 32; o <<= 1) {
        int y = __shfl_up_sync(0xffffffff, x, o);
        if (lane >= o) x += y;
    }
    int warpsum = __shfl_sync(0xffffffff, x, 31);
    int base = 0;
    if (lane == 31) base = atomicAdd(&g_total, warpsum);
    base = __shfl_sync(0xffffffff, base, 31);
    int start = base + x - d;
    if (i < N_NODES) { g_start[i] = start; g_cur[i] = start; }
}

// ---------------- CSR fill ---------------------------------------------------
__global__ void k_fill(const int* __restrict__ ei) {
    int e = blockIdx.x * blockDim.x + threadIdx.x;
    if (e < N_EDGES) {
        int s = ei[e];
        int d = ei[N_EDGES + e];
        int slot = atomicAdd(&g_cur[d], 1);
        g_csr[slot] = s;
    }
}

// ---------------- GEMM: out16 = half((X @ W) * dinv[row]) -------------------
// 128x128 tile, 256 threads, 8x8 micro-tile, packed fma.rn.f32x2 inner loop.
// HALF_IN selects fp16 vs fp32 input rows. Accumulation is fp32 throughout.
template <bool HALF_IN>
__global__ __launch_bounds__(256) void k_gemm(const void* __restrict__ Xv,
                                              const float* __restrict__ W,
                                              __half* __restrict__ out) {
    __shared__ float Ws[16 * 128];         // Ws[kk][col]
    __shared__ float Xs[16 * 132];         // Xs[kk][row]

    int tid = threadIdx.x;
    int tx = tid & 15;
    int ty = tid >> 4;
    int row0 = blockIdx.x * 128;

    unsigned long long acc2[8][4];
#pragma unroll
    for (int i = 0; i < 8; i++)
#pragma unroll
        for (int j = 0; j < 4; j++) acc2[i][j] = 0ull;

    for (int k0 = 0; k0 < F; k0 += 16) {
        const float4* W4 = (const float4*)(W + k0 * F);
        float4* Ws4 = (float4*)Ws;
#pragma unroll
        for (int t = tid; t < 512; t += 256) Ws4[t] = __ldg(&W4[t]);

        if (HALF_IN) {
            const __half* Xh = (const __half*)Xv;
            // 128 rows x 2 chunks of 8 halfs (16B) = 256 tasks
            int t = tid;
            {
                int rr = t >> 1;
                int c  = t & 1;
                int grow = row0 + rr;
                uint4 raw = make_uint4(0u, 0u, 0u, 0u);
                if (grow < N_NODES)
                    raw = __ldg((const uint4*)&Xh[grow * F + k0 + c * 8]);
                const __half2* h2 = (const __half2*)&raw;
#pragma unroll
                for (int j = 0; j < 4; j++) {
                    float2 f = __half22float2(h2[j]);
                    Xs[(c * 8 + j * 2 + 0) * 132 + rr] = f.x;
                    Xs[(c * 8 + j * 2 + 1) * 132 + rr] = f.y;
                }
            }
        } else {
            const float* X = (const float*)Xv;
#pragma unroll
            for (int t = tid; t < 512; t += 256) {
                int rr = t >> 2;
                int c  = t & 3;
                int grow = row0 + rr;
                float4 xv = make_float4(0.f, 0.f, 0.f, 0.f);
                if (grow < N_NODES)
                    xv = __ldg((const float4*)&X[grow * F + k0 + c * 4]);
                Xs[(c * 4 + 0) * 132 + rr] = xv.x;
                Xs[(c * 4 + 1) * 132 + rr] = xv.y;
                Xs[(c * 4 + 2) * 132 + rr] = xv.z;
                Xs[(c * 4 + 3) * 132 + rr] = xv.w;
            }
        }
        __syncthreads();

#pragma unroll
        for (int kk = 0; kk < 16; kk++) {
            float4 a0 = *(const float4*)&Xs[kk * 132 + ty * 4];
            float4 a1 = *(const float4*)&Xs[kk * 132 + 64 + ty * 4];
            float4 b0 = *(const float4*)&Ws[kk * 128 + tx * 4];
            float4 b1 = *(const float4*)&Ws[kk * 128 + 64 + tx * 4];

            unsigned long long bp[4];
            asm("mov.b64 %0, {%1,%2};" : "=l"(bp[0]) : "f"(b0.x), "f"(b0.y));
            asm("mov.b64 %0, {%1,%2};" : "=l"(bp[1]) : "f"(b0.z), "f"(b0.w));
            asm("mov.b64 %0, {%1,%2};" : "=l"(bp[2]) : "f"(b1.x), "f"(b1.y));
            asm("mov.b64 %0, {%1,%2};" : "=l"(bp[3]) : "f"(b1.z), "f"(b1.w));

            float a[8] = {a0.x, a0.y, a0.z, a0.w, a1.x, a1.y, a1.z, a1.w};
#pragma unroll
            for (int i = 0; i < 8; i++) {
                unsigned long long ad;
                asm("mov.b64 %0, {%1,%1};" : "=l"(ad) : "f"(a[i]));
#pragma unroll
                for (int j = 0; j < 4; j++)
                    asm("fma.rn.f32x2 %0, %1, %2, %0;"
                        : "+l"(acc2[i][j]) : "l"(ad), "l"(bp[j]));
            }
        }
        __syncthreads();
    }

    // epilogue: unpack, scale by dinv[row], convert to fp16, 8B stores
#pragma unroll
    for (int i = 0; i < 8; i++) {
        int grow = row0 + ((i < 4) ? (ty * 4 + i) : (64 + ty * 4 + (i - 4)));
        if (grow < N_NODES) {
            float dv = g_dinv[grow];
            float c0, c1, c2, c3, c4, c5, c6, c7;
            asm("mov.b64 {%0,%1}, %2;" : "=f"(c0), "=f"(c1) : "l"(acc2[i][0]));
            asm("mov.b64 {%0,%1}, %2;" : "=f"(c2), "=f"(c3) : "l"(acc2[i][1]));
            asm("mov.b64 {%0,%1}, %2;" : "=f"(c4), "=f"(c5) : "l"(acc2[i][2]));
            asm("mov.b64 {%0,%1}, %2;" : "=f"(c6), "=f"(c7) : "l"(acc2[i][3]));
            __half2 h0 = __float22half2_rn(make_float2(c0 * dv, c1 * dv));
            __half2 h1 = __float22half2_rn(make_float2(c2 * dv, c3 * dv));
            __half2 h2 = __float22half2_rn(make_float2(c4 * dv, c5 * dv));
            __half2 h3 = __float22half2_rn(make_float2(c6 * dv, c7 * dv));
            uint2 p0, p1;
            p0.x = *(unsigned*)&h0; p0.y = *(unsigned*)&h1;
            p1.x = *(unsigned*)&h2; p1.y = *(unsigned*)&h3;
            *(uint2*)&out[grow * F + tx * 4]      = p0;
            *(uint2*)&out[grow * F + 64 + tx * 4] = p1;
        }
    }
}

// ---------------- gather: h[n] = relu(dinv[n]*(hp[n] + sum_in hp[src]) + b)
// warp per node over fp16 rows (256B). fp32 accumulation.
__global__ __launch_bounds__(256) void k_gather(const __half* __restrict__ hp,
                                                __half* __restrict__ out_,
                                                const float* __restrict__ bias,
                                                const int* __restrict__ batch,
                                                int layer) {
    int warp = (blockIdx.x * blockDim.x + threadIdx.x) >> 5;
    int lane = threadIdx.x & 31;
    if (warp >= N_NODES) return;
    int node = warp;

    // lane covers features [lane*4, lane*4+3]: 8 bytes fp16 per lane
    uint2 raw = __ldg((const uint2*)&hp[node * F + lane * 4]);
    float2 f0 = __half22float2(*(const __half2*)&raw.x);
    float2 f1 = __half22float2(*(const __half2*)&raw.y);
    float4 acc = make_float4(f0.x, f0.y, f1.x, f1.y);   // self loop

    int start = g_start[node];
    int deg   = g_deg[node];

    for (int base = 0; base < deg; base += 32) {
        int rem = deg - base;
        int n = (rem < 32) ? rem : 32;
        int idx = (lane < n) ? __ldg(&g_csr[start + base + lane]) : 0;
#pragma unroll 4
        for (int j = 0; j < n; j++) {
            int s = __shfl_sync(0xffffffff, idx, j);
            uint2 rv = __ldg((const uint2*)&hp[s * F + lane * 4]);
            float2 v0 = __half22float2(*(const __half2*)&rv.x);
            float2 v1 = __half22float2(*(const __half2*)&rv.y);
            acc.x += v0.x; acc.y += v0.y; acc.z += v1.x; acc.w += v1.y;
        }
    }

    float dv = g_dinv[node];
    float4 b4 = __ldg(&((const float4*)bias)[lane]);
    float4 r;
    r.x = fmaxf(acc.x * dv + b4.x, 0.0f);
    r.y = fmaxf(acc.y * dv + b4.y, 0.0f);
    r.z = fmaxf(acc.z * dv + b4.z, 0.0f);
    r.w = fmaxf(acc.w * dv + b4.w, 0.0f);

    if (layer == 1) {
        __half2 o0 = __float22half2_rn(make_float2(r.x, r.y));
        __half2 o1 = __float22half2_rn(make_float2(r.z, r.w));
        uint2 p; p.x = *(unsigned*)&o0; p.y = *(unsigned*)&o1;
        *(uint2*)&out_[node * F + lane * 4] = p;
    } else {
        int g = __ldg(&batch[node]);
        const float4* p = &((const float4*)g_pool)[g * 32 + lane];
        asm volatile("red.global.add.v4.f32 [%0], {%1, %2, %3, %4};"
                     :: "l"(p), "f"(r.x), "f"(r.y), "f"(r.z), "f"(r.w)
                     : "memory");
    }
}

// ---------------- head: out[g] = sigmoid(dot(pool[g]/cnt, Wl) + bl) --------
__global__ void k_final(const float* __restrict__ Wl,
                        const float* __restrict__ bl,
                        float* __restrict__ out) {
    __shared__ float Wls[F];
    int tid = threadIdx.x;
    if (tid < F) Wls[tid] = Wl[tid];
    __syncthreads();

    int g = blockIdx.x * blockDim.x + tid;
    if (g < NUM_G) {
        float sum = 0.0f;
#pragma unroll 8
        for (int k = 0; k < F; k++) sum += g_pool[g * F + k] * Wls[k];
        float c = fmaxf(g_cnt[g], 1.0f);
        float z = sum / c + bl[0];
        out[g] = 1.0f / (1.0f + expf(-z));
    }
}

// ---------------- launch ----------------------------------------------------
extern "C" void kernel_launch(void* const* d_in, const int* in_sizes, int n_in,
                              void* d_out, int out_size) {
    const float* x     = (const float*)d_in[0];
    const int*   ei    = (const int*)d_in[1];
    const int*   batch = (const int*)d_in[2];
    const float* W1    = (const float*)d_in[3];
    const float* b1    = (const float*)d_in[4];
    const float* W2    = (const float*)d_in[5];
    const float* b2    = (const float*)d_in[6];
    const float* Wl    = (const float*)d_in[7];
    const float* bl    = (const float*)d_in[8];
    float* out = (float*)d_out;

    __half* hA; cudaGetSymbolAddress((void**)&hA, g_h16A);
    __half* hB; cudaGetSymbolAddress((void**)&hB, g_h16B);

    k_init<<<(NUM_G * F + 255) / 256, 256>>>();
    k_deg<<<(N_EDGES + 255) / 256, 256>>>(ei, batch);
    k_alloc<<<(N_NODES + 255) / 256, 256>>>();
    k_fill<<<(N_EDGES + 255) / 256, 256>>>(ei);

    int gemm_blocks = (N_NODES + 127) / 128;
    int gth_blocks  = (N_NODES * 32 + 255) / 256;

    // layer 1: x -> hp1 (hA) -> h1 (hB)
    k_gemm<false><<<gemm_blocks, 256>>>((const void*)x, W1, hA);
    k_gather<<<gth_blocks, 256>>>(hA, hB, b1, batch, 1);

    // layer 2: h1 (hB) -> hp2 (hA) -> pool
    k_gemm<true><<<gemm_blocks, 256>>>((const void*)hB, W2, hA);
    k_gather<<<gth_blocks, 256>>>(hA, nullptr, b2, batch, 2);

    k_final<<<(NUM_G + 255) / 256, 256>>>(Wl, bl, out);
}

// round 9
// speedup vs baseline: 3.5136x; 1.3497x over previous
#include <cuda_runtime.h>
#include <cuda_fp16.h>
#include <math.h>

#define N_NODES   50000
#define N_EDGES   800000
#define NUM_G     512
#define F         128
#define PADH      136        // smem row stride in halves (272B, 16B-aligned)

// ---------------- device scratch (globals: allocation-free) ----------------
__device__ float  g_dinv[N_NODES];
__device__ int    g_deg[N_NODES];
__device__ int    g_start[N_NODES];
__device__ int    g_cur[N_NODES];
__device__ int    g_csr[N_EDGES];
__device__ int    g_total;
__device__ __half g_h16X[N_NODES * F];   // fp16 copy of input x
__device__ __half g_h16A[N_NODES * F];   // hp (scaled X@W)
__device__ __half g_h16B[N_NODES * F];   // h1 (post-relu)
__device__ __half g_w16a[F * F];         // fp16 W1
__device__ __half g_w16b[F * F];         // fp16 W2
__device__ float  g_pool[NUM_G * F];
__device__ float  g_cnt[NUM_G];

// ---------------- init: zero counters + convert W1/W2 to fp16 --------------
__global__ void k_init(const float* __restrict__ W1,
                       const float* __restrict__ W2) {
    int i = blockIdx.x * blockDim.x + threadIdx.x;
    if (i < N_NODES) g_deg[i] = 0;
    if (i < NUM_G * F) g_pool[i] = 0.0f;
    if (i < NUM_G) g_cnt[i] = 0.0f;
    if (i == 0) g_total = 0;
    if (i < F * F) g_w16a[i] = __float2half_rn(W1[i]);
    else if (i < 2 * F * F) g_w16b[i - F * F] = __float2half_rn(W2[i - F * F]);
}

// ---------------- degree + graph-size histograms + x->fp16 convert ---------
// grid covers 800000 threads: exactly N_EDGES and exactly N_NODES*F/8.
__global__ void k_deg(const int* __restrict__ ei,
                      const int* __restrict__ batch,
                      const float* __restrict__ x) {
    int i = blockIdx.x * blockDim.x + threadIdx.x;
    if (i < N_EDGES) {
        atomicAdd(&g_deg[ei[N_EDGES + i]], 1);
        // convert 8 x elements
        float4 v0 = __ldg((const float4*)&x[i * 8]);
        float4 v1 = __ldg((const float4*)&x[i * 8 + 4]);
        __half2 h0 = __float22half2_rn(make_float2(v0.x, v0.y));
        __half2 h1 = __float22half2_rn(make_float2(v0.z, v0.w));
        __half2 h2 = __float22half2_rn(make_float2(v1.x, v1.y));
        __half2 h3 = __float22half2_rn(make_float2(v1.z, v1.w));
        uint4 p;
        p.x = *(unsigned*)&h0; p.y = *(unsigned*)&h1;
        p.z = *(unsigned*)&h2; p.w = *(unsigned*)&h3;
        *(uint4*)&g_h16X[i * 8] = p;
    }
    if (i < N_NODES) atomicAdd(&g_cnt[batch[i]], 1.0f);
}

// ---------------- CSR offset alloc (warp-scan) + dinv = rsqrt(deg+1) --------
__global__ void k_alloc() {
    int i = blockIdx.x * blockDim.x + threadIdx.x;
    int lane = threadIdx.x & 31;
    int d = (i < N_NODES) ? g_deg[i] : 0;
    if (i < N_NODES) g_dinv[i] = rsqrtf((float)d + 1.0f);
    int x = d;
#pragma unroll
    for (int o = 1; o < 32; o <<= 1) {
        int y = __shfl_up_sync(0xffffffff, x, o);
        if (lane >= o) x += y;
    }
    int warpsum = __shfl_sync(0xffffffff, x, 31);
    int base = 0;
    if (lane == 31) base = atomicAdd(&g_total, warpsum);
    base = __shfl_sync(0xffffffff, base, 31);
    int start = base + x - d;
    if (i < N_NODES) { g_start[i] = start; g_cur[i] = start; }
}

// ---------------- CSR fill ---------------------------------------------------
__global__ void k_fill(const int* __restrict__ ei) {
    int e = blockIdx.x * blockDim.x + threadIdx.x;
    if (e < N_EDGES) {
        int s = ei[e];
        int d = ei[N_EDGES + e];
        int slot = atomicAdd(&g_cur[d], 1);
        g_csr[slot] = s;
    }
}

// ---------------- tensor-core GEMM: out16 = half((X @ W) * dinv[row]) ------
// 128x128x128 per CTA, 8 warps (4x2), mma.sync.m16n8k16 f16 -> f32 acc.
// Whole W and one 128-row X tile staged in dynamic smem (69632 B).
__global__ __launch_bounds__(256) void k_gemm_mma(const __half* __restrict__ Xh,
                                                  const __half* __restrict__ Wh,
                                                  __half* __restrict__ out) {
    extern __shared__ __half sm[];
    __half* Xs = sm;                  // [128][PADH]
    __half* Ws = sm + 128 * PADH;     // [128][PADH]

    int tid = threadIdx.x;
    int row0 = blockIdx.x * 128;

    // stage X tile (zero-pad OOB rows) and full W
#pragma unroll
    for (int c = tid; c < 2048; c += 256) {
        int r = c >> 4;
        int p = (c & 15) * 8;
        uint4 v = make_uint4(0u, 0u, 0u, 0u);
        int gr = row0 + r;
        if (gr < N_NODES) v = __ldg((const uint4*)&Xh[gr * F + p]);
        *(uint4*)&Xs[r * PADH + p] = v;
        uint4 w = __ldg((const uint4*)&Wh[r * F + p]);
        *(uint4*)&Ws[r * PADH + p] = w;
    }
    __syncthreads();

    int warp = tid >> 5, lane = tid & 31;
    int wm = (warp & 3) * 32;      // warp m-offset
    int wn = (warp >> 2) * 64;     // warp n-offset

    float acc[2][8][4];
#pragma unroll
    for (int mi = 0; mi < 2; mi++)
#pragma unroll
        for (int ni = 0; ni < 8; ni++)
#pragma unroll
            for (int k = 0; k < 4; k++) acc[mi][ni][k] = 0.0f;

    unsigned xbase = (unsigned)__cvta_generic_to_shared(Xs);
    unsigned wbase = (unsigned)__cvta_generic_to_shared(Ws);

#pragma unroll
    for (int k0 = 0; k0 < 128; k0 += 16) {
        unsigned a[2][4];
#pragma unroll
        for (int mi = 0; mi < 2; mi++) {
            int r = wm + mi * 16 + (lane & 15);
            int cp = k0 + (lane >> 4) * 8;
            unsigned addr = xbase + (unsigned)(r * PADH + cp) * 2u;
            asm volatile("ldmatrix.sync.aligned.m8n8.x4.shared.b16 {%0,%1,%2,%3}, [%4];"
                : "=r"(a[mi][0]), "=r"(a[mi][1]), "=r"(a[mi][2]), "=r"(a[mi][3])
                : "r"(addr));
        }
#pragma unroll
        for (int ni = 0; ni < 8; ni++) {
            int krow = k0 + (lane & 15);
            int col  = wn + ni * 8;
            unsigned addr = wbase + (unsigned)(krow * PADH + col) * 2u;
            unsigned b0, b1;
            asm volatile("ldmatrix.sync.aligned.m8n8.x2.trans.shared.b16 {%0,%1}, [%2];"
                : "=r"(b0), "=r"(b1) : "r"(addr));
#pragma unroll
            for (int mi = 0; mi < 2; mi++) {
                asm volatile("mma.sync.aligned.m16n8k16.row.col.f32.f16.f16.f32 "
                    "{%0,%1,%2,%3},{%4,%5,%6,%7},{%8,%9},{%0,%1,%2,%3};"
                    : "+f"(acc[mi][ni][0]), "+f"(acc[mi][ni][1]),
                      "+f"(acc[mi][ni][2]), "+f"(acc[mi][ni][3])
                    : "r"(a[mi][0]), "r"(a[mi][1]), "r"(a[mi][2]), "r"(a[mi][3]),
                      "r"(b0), "r"(b1));
            }
        }
    }

    // epilogue: scale by dinv[row], fp16 stores
    int g  = lane >> 2;
    int tc = (lane & 3) * 2;
#pragma unroll
    for (int mi = 0; mi < 2; mi++) {
        int ra = row0 + wm + mi * 16 + g;
        int rb = ra + 8;
        float dva = (ra < N_NODES) ? g_dinv[ra] : 0.0f;
        float dvb = (rb < N_NODES) ? g_dinv[rb] : 0.0f;
#pragma unroll
        for (int ni = 0; ni < 8; ni++) {
            int col = wn + ni * 8 + tc;
            if (ra < N_NODES) {
                __half2 h = __float22half2_rn(
                    make_float2(acc[mi][ni][0] * dva, acc[mi][ni][1] * dva));
                *(__half2*)&out[ra * F + col] = h;
            }
            if (rb < N_NODES) {
                __half2 h = __float22half2_rn(
                    make_float2(acc[mi][ni][2] * dvb, acc[mi][ni][3] * dvb));
                *(__half2*)&out[rb * F + col] = h;
            }
        }
    }
}

// ---------------- gather: h[n] = relu(dinv[n]*(hp[n] + sum_in hp[src]) + b)
// warp per node over fp16 rows (256B). fp32 accumulation.
__global__ __launch_bounds__(256) void k_gather(const __half* __restrict__ hp,
                                                __half* __restrict__ out_,
                                                const float* __restrict__ bias,
                                                const int* __restrict__ batch,
                                                int layer) {
    int warp = (blockIdx.x * blockDim.x + threadIdx.x) >> 5;
    int lane = threadIdx.x & 31;
    if (warp >= N_NODES) return;
    int node = warp;

    uint2 raw = __ldg((const uint2*)&hp[node * F + lane * 4]);
    float2 f0 = __half22float2(*(const __half2*)&raw.x);
    float2 f1 = __half22float2(*(const __half2*)&raw.y);
    float4 acc = make_float4(f0.x, f0.y, f1.x, f1.y);   // self loop

    int start = g_start[node];
    int deg   = g_deg[node];

    for (int base = 0; base < deg; base += 32) {
        int rem = deg - base;
        int n = (rem < 32) ? rem : 32;
        int idx = (lane < n) ? __ldg(&g_csr[start + base + lane]) : 0;
#pragma unroll 4
        for (int j = 0; j < n; j++) {
            int s = __shfl_sync(0xffffffff, idx, j);
            uint2 rv = __ldg((const uint2*)&hp[s * F + lane * 4]);
            float2 v0 = __half22float2(*(const __half2*)&rv.x);
            float2 v1 = __half22float2(*(const __half2*)&rv.y);
            acc.x += v0.x; acc.y += v0.y; acc.z += v1.x; acc.w += v1.y;
        }
    }

    float dv = g_dinv[node];
    float4 b4 = __ldg(&((const float4*)bias)[lane]);
    float4 r;
    r.x = fmaxf(acc.x * dv + b4.x, 0.0f);
    r.y = fmaxf(acc.y * dv + b4.y, 0.0f);
    r.z = fmaxf(acc.z * dv + b4.z, 0.0f);
    r.w = fmaxf(acc.w * dv + b4.w, 0.0f);

    if (layer == 1) {
        __half2 o0 = __float22half2_rn(make_float2(r.x, r.y));
        __half2 o1 = __float22half2_rn(make_float2(r.z, r.w));
        uint2 p; p.x = *(unsigned*)&o0; p.y = *(unsigned*)&o1;
        *(uint2*)&out_[node * F + lane * 4] = p;
    } else {
        int g = __ldg(&batch[node]);
        const float4* p = &((const float4*)g_pool)[g * 32 + lane];
        asm volatile("red.global.add.v4.f32 [%0], {%1, %2, %3, %4};"
                     :: "l"(p), "f"(r.x), "f"(r.y), "f"(r.z), "f"(r.w)
                     : "memory");
    }
}

// ---------------- head: out[g] = sigmoid(dot(pool[g]/cnt, Wl) + bl) --------
__global__ void k_final(const float* __restrict__ Wl,
                        const float* __restrict__ bl,
                        float* __restrict__ out) {
    __shared__ float Wls[F];
    int tid = threadIdx.x;
    if (tid < F) Wls[tid] = Wl[tid];
    __syncthreads();

    int g = blockIdx.x * blockDim.x + tid;
    if (g < NUM_G) {
        float sum = 0.0f;
#pragma unroll 8
        for (int k = 0; k < F; k++) sum += g_pool[g * F + k] * Wls[k];
        float c = fmaxf(g_cnt[g], 1.0f);
        float z = sum / c + bl[0];
        out[g] = 1.0f / (1.0f + expf(-z));
    }
}

// ---------------- launch ----------------------------------------------------
extern "C" void kernel_launch(void* const* d_in, const int* in_sizes, int n_in,
                              void* d_out, int out_size) {
    const float* x     = (const float*)d_in[0];
    const int*   ei    = (const int*)d_in[1];
    const int*   batch = (const int*)d_in[2];
    const float* W1    = (const float*)d_in[3];
    const float* b1    = (const float*)d_in[4];
    const float* W2    = (const float*)d_in[5];
    const float* b2    = (const float*)d_in[6];
    const float* Wl    = (const float*)d_in[7];
    const float* bl    = (const float*)d_in[8];
    float* out = (float*)d_out;

    __half* hX; cudaGetSymbolAddress((void**)&hX, g_h16X);
    __half* hA; cudaGetSymbolAddress((void**)&hA, g_h16A);
    __half* hB; cudaGetSymbolAddress((void**)&hB, g_h16B);
    __half* wA; cudaGetSymbolAddress((void**)&wA, g_w16a);
    __half* wB; cudaGetSymbolAddress((void**)&wB, g_w16b);

    const int smem_bytes = 2 * 128 * PADH * sizeof(__half);   // 69632
    cudaFuncSetAttribute(k_gemm_mma,
                         cudaFuncAttributeMaxDynamicSharedMemorySize, smem_bytes);

    k_init<<<(NUM_G * F + 255) / 256, 256>>>(W1, W2);
    k_deg<<<(N_EDGES + 255) / 256, 256>>>(ei, batch, x);
    k_alloc<<<(N_NODES + 255) / 256, 256>>>();
    k_fill<<<(N_EDGES + 255) / 256, 256>>>(ei);

    int gemm_blocks = (N_NODES + 127) / 128;
    int gth_blocks  = (N_NODES * 32 + 255) / 256;

    // layer 1: x16 -> hp1 (hA) -> h1 (hB)
    k_gemm_mma<<<gemm_blocks, 256, smem_bytes>>>(hX, wA, hA);
    k_gather<<<gth_blocks, 256>>>(hA, hB, b1, batch, 1);

    // layer 2: h1 (hB) -> hp2 (hA) -> pool
    k_gemm_mma<<<gemm_blocks, 256, smem_bytes>>>(hB, wB, hA);
    k_gather<<<gth_blocks, 256>>>(hA, nullptr, b2, batch, 2);

    k_final<<<(NUM_G + 255) / 256, 256>>>(Wl, bl, out);
}